// round 5
// baseline (speedup 1.0000x reference)
#include <cuda_runtime.h>
#include <math.h>

#define NRULES 1024
#define DMODEL 128
#define EDIM   256
#define TMAX   16
#define CAP    96   // max tokens per rule (P(Poisson(8) > 96) ~ 0)
#define XSTR   20   // [d][t] tile stride (mult of 4 -> aligned float4 at t-quads)
#define HSTR   20   // [e][t] tile stride

// 0 = int64 layout, 1 = int32 layout. Monotonic; identical inputs every replay.
__device__ int g_is64 = 0;

// If rules is int64, every odd 32-bit word is 0 (values in [0,1024)).
// If int32, odd words are random rule ids; P(256 random ids all zero) ~ 1e-771.
__global__ void detect_kernel(const unsigned int* __restrict__ raw) {
    int i = threadIdx.x;
    if (raw[2 * i + 1] != 0u) atomicOr(&g_is64, 1);
}

__device__ __forceinline__ float gelu_exact(float v) {
    return 0.5f * v * (1.0f + erff(v * 0.70710678118654752f));
}

// Chunk body, NQ = number of active token-quads (1..4). 4x4 register blocking.
template<int NQ>
__device__ __forceinline__ void ffn_chunk(
    const float* __restrict__ x,
    const float* __restrict__ W1,
    const float* __restrict__ W2,
    const float* __restrict__ b1r,
    const float* __restrict__ b2r,
    float* xs, float* hs, const int* toks,
    float* __restrict__ out,
    int T, int tid)
{
    // ---- load x tile, transposed: xs[d][t] (coalesced along d) ----
    for (int i = tid; i < NQ * 4 * DMODEL; i += 256) {
        int t = i >> 7;
        int d = i & (DMODEL - 1);
        float v = (t < T) ? x[(size_t)toks[t] * DMODEL + d] : 0.0f;
        xs[d * XSTR + t] = v;
    }
    __syncthreads();

    // ---- layer 1: thread owns e-quad x t-quad. tid = tq1*64 + equad ----
    {
        const int equad = tid & 63;
        const int tq1   = tid >> 6;          // warp-uniform
        if (tq1 < NQ) {
            const int e0 = equad * 4;
            const int t0 = tq1 * 4;
            const float4 bv = *(const float4*)&b1r[e0];
            float acc[16];
#pragma unroll
            for (int k = 0; k < 4; k++) {
                acc[0 * 4 + k] = bv.x; acc[1 * 4 + k] = bv.y;
                acc[2 * 4 + k] = bv.z; acc[3 * 4 + k] = bv.w;
            }
#pragma unroll 2
            for (int d = 0; d < DMODEL; d++) {
                const float4 wv = *(const float4*)&W1[d * EDIM + e0];  // LDG.128 coalesced
                const float4 xv = *(const float4*)&xs[d * XSTR + t0];  // broadcast LDS.128
                const float wj[4] = {wv.x, wv.y, wv.z, wv.w};
                const float xk[4] = {xv.x, xv.y, xv.z, xv.w};
#pragma unroll
                for (int j = 0; j < 4; j++)
#pragma unroll
                    for (int k = 0; k < 4; k++)
                        acc[j * 4 + k] += wj[j] * xk[k];
            }
            // gelu + store hs[e][t]
#pragma unroll
            for (int j = 0; j < 4; j++) {
                float4 hv;
                hv.x = gelu_exact(acc[j * 4 + 0]);
                hv.y = gelu_exact(acc[j * 4 + 1]);
                hv.z = gelu_exact(acc[j * 4 + 2]);
                hv.w = gelu_exact(acc[j * 4 + 3]);
                *(float4*)&hs[(e0 + j) * HSTR + t0] = hv;
            }
        }
    }
    __syncthreads();   // hs ready; xs reads done -> xs reusable as reduction buf

    // ---- layer 2: thread owns d-quad x t-quad, e split in halves ----
    const int dquad = tid & 31;
    const int tq2   = (tid >> 5) & 3;        // warp-uniform
    const int eh    = tid >> 7;              // warp-uniform
    const int d0 = dquad * 4;
    const int t0 = tq2 * 4;

    float acc2[16];
    if (tq2 < NQ) {
#pragma unroll
        for (int i = 0; i < 16; i++) acc2[i] = 0.0f;
        const int ebase = eh << 7;
#pragma unroll 2
        for (int ee = 0; ee < 128; ee++) {
            const int e = ebase + ee;
            const float4 wv = *(const float4*)&W2[(size_t)e * DMODEL + d0]; // LDG.128
            const float4 hv = *(const float4*)&hs[e * HSTR + t0];           // broadcast LDS.128
            const float wj[4] = {wv.x, wv.y, wv.z, wv.w};
            const float hk[4] = {hv.x, hv.y, hv.z, hv.w};
#pragma unroll
            for (int j = 0; j < 4; j++)
#pragma unroll
                for (int k = 0; k < 4; k++)
                    acc2[j * 4 + k] += wj[j] * hk[k];
        }
        if (eh == 1) {   // dump partials into xs reused as [d][t]
#pragma unroll
            for (int j = 0; j < 4; j++) {
                float4 pv;
                pv.x = acc2[j * 4 + 0]; pv.y = acc2[j * 4 + 1];
                pv.z = acc2[j * 4 + 2]; pv.w = acc2[j * 4 + 3];
                *(float4*)&xs[(d0 + j) * XSTR + t0] = pv;
            }
        }
    }
    __syncthreads();

    if (tq2 < NQ && eh == 0) {
        const float4 bv2 = *(const float4*)&b2r[d0];
        const float bj[4] = {bv2.x, bv2.y, bv2.z, bv2.w};
#pragma unroll
        for (int j = 0; j < 4; j++) {
            const float4 pv = *(const float4*)&xs[(d0 + j) * XSTR + t0];
            acc2[j * 4 + 0] += pv.x;
            acc2[j * 4 + 1] += pv.y;
            acc2[j * 4 + 2] += pv.z;
            acc2[j * 4 + 3] += pv.w;
        }
#pragma unroll
        for (int k = 0; k < 4; k++) {
            const int t = t0 + k;
            if (t < T) {
                float4 o;
                o.x = acc2[0 * 4 + k] + bj[0];
                o.y = acc2[1 * 4 + k] + bj[1];
                o.z = acc2[2 * 4 + k] + bj[2];
                o.w = acc2[3 * 4 + k] + bj[3];
                *(float4*)&out[(size_t)toks[t] * DMODEL + d0] = o;   // STG.128 coalesced
            }
        }
    }
    __syncthreads();  // protect toks/xs before next chunk
}

// One block per rule, 256 threads, 4 CTAs/SM (RF cap: 64 regs).
__global__ __launch_bounds__(256, 4) void ffn_kernel(
    const float* __restrict__ x,
    const void*  __restrict__ rules,
    const float* __restrict__ w1,
    const float* __restrict__ b1,
    const float* __restrict__ w2,
    const float* __restrict__ b2,
    float* __restrict__ out,
    int n)
{
    const int r   = blockIdx.x;
    const int tid = threadIdx.x;

    __shared__ float xs[DMODEL * XSTR];
    __shared__ float hs[EDIM * HSTR];
    __shared__ int   toks[CAP];
    __shared__ int   cnt;

    if (tid == 0) cnt = 0;
    __syncthreads();

    // ---- self-gather this rule's tokens (order irrelevant) ----
    if (g_is64 == 0) {
        const long long* rl = (const long long*)rules;
        for (int i = tid; i < n; i += 256)
            if ((int)rl[i] == r) { int p = atomicAdd(&cnt, 1); if (p < CAP) toks[p] = i; }
    } else {
        const int* rl = (const int*)rules;
        for (int i = tid; i < n; i += 256)
            if (rl[i] == r) { int p = atomicAdd(&cnt, 1); if (p < CAP) toks[p] = i; }
    }
    __syncthreads();

    const int count = min(cnt, CAP);
    if (count == 0) return;

    const float* W1  = w1 + (size_t)r * DMODEL * EDIM;
    const float* W2  = w2 + (size_t)r * EDIM * DMODEL;
    const float* b1r = b1 + (size_t)r * EDIM;
    const float* b2r = b2 + (size_t)r * DMODEL;

    for (int base = 0; base < count; base += TMAX) {
        const int T = min(TMAX, count - base);
        switch ((T + 3) >> 2) {   // uniform per block
            case 1:  ffn_chunk<1>(x, W1, W2, b1r, b2r, xs, hs, toks + base, out, T, tid); break;
            case 2:  ffn_chunk<2>(x, W1, W2, b1r, b2r, xs, hs, toks + base, out, T, tid); break;
            case 3:  ffn_chunk<3>(x, W1, W2, b1r, b2r, xs, hs, toks + base, out, T, tid); break;
            default: ffn_chunk<4>(x, W1, W2, b1r, b2r, xs, hs, toks + base, out, T, tid); break;
        }
    }
}

extern "C" void kernel_launch(void* const* d_in, const int* in_sizes, int n_in,
                              void* d_out, int out_size)
{
    const float* x     = (const float*)d_in[0];
    const void*  rules = d_in[1];
    const float* w1    = (const float*)d_in[2];
    const float* b1    = (const float*)d_in[3];
    const float* w2    = (const float*)d_in[4];
    const float* b2    = (const float*)d_in[5];
    float*       out   = (float*)d_out;

    const int n = in_sizes[1];

    detect_kernel<<<1, 256>>>((const unsigned int*)rules);  // probes 256 odd words (in-bounds either dtype)
    ffn_kernel<<<NRULES, 256>>>(x, rules, w1, b1, w2, b2, out, n);
}

// round 6
// speedup vs baseline: 1.8968x; 1.8968x over previous
#include <cuda_runtime.h>
#include <math.h>

#define NRULES 1024
#define DMODEL 128
#define EDIM   256
#define TMAX   8
#define CAP    96   // max tokens per rule (P(Poisson(8) > 96) ~ 0)
#define XSTR   12   // [d][t] tile stride (mult of 4 -> aligned float4 at t-quads)
#define HSTR   12   // [e][t] tile stride

// 0 = int64 layout, 1 = int32 layout. Monotonic; identical inputs every replay.
__device__ int g_is64 = 0;

// If rules is int64, every odd 32-bit word is 0 (values in [0,1024)).
// If int32, odd words are random rule ids; P(256 random ids all zero) ~ 0.
__global__ void detect_kernel(const unsigned int* __restrict__ raw) {
    int i = threadIdx.x;
    if (raw[2 * i + 1] != 0u) atomicOr(&g_is64, 1);
}

__device__ __forceinline__ float gelu_exact(float v) {
    return 0.5f * v * (1.0f + erff(v * 0.70710678118654752f));
}

// Chunk body. Q = active token-quads (1..2); ALL 256 threads work in both layers.
// Layer1: thread owns e-column tid, Q*4 token accumulators.
// Layer2: thread owns d-column tid&127, e-half tid>>7.
template<int Q>
__device__ __forceinline__ void ffn_chunk(
    const float* __restrict__ x,
    const float* __restrict__ W1,
    const float* __restrict__ W2,
    float b1v, float b2v,
    float* xs, float* hs, const int* toks,
    float* __restrict__ out,
    int T, int tid, int half, int dcol)
{
    // ---- load x tile, transposed: xs[d][t] (coalesced along d) ----
    for (int i = tid; i < Q * 4 * DMODEL; i += 256) {
        int t = i >> 7;
        int d = i & (DMODEL - 1);
        xs[d * XSTR + t] = (t < T) ? x[(size_t)toks[t] * DMODEL + d] : 0.0f;
    }
    __syncthreads();

    // ---- layer 1: h[t][e] = sum_d xs[d][t] * W1[d][e] + b1[e] ----
    float acc[Q * 4];
#pragma unroll
    for (int t = 0; t < Q * 4; t++) acc[t] = b1v;

    {
        const float* wp = W1 + tid;
#pragma unroll 1
        for (int d = 0; d < DMODEL; d += 4) {
            // 4 independent LDGs hoisted -> MLP >= 4
            float w0 = wp[(d + 0) * EDIM];
            float w1 = wp[(d + 1) * EDIM];
            float w2 = wp[(d + 2) * EDIM];
            float w3 = wp[(d + 3) * EDIM];
#pragma unroll
            for (int q = 0; q < Q; q++) {
                float4 x0 = *(const float4*)&xs[(d + 0) * XSTR + q * 4];
                float4 x1 = *(const float4*)&xs[(d + 1) * XSTR + q * 4];
                float4 x2 = *(const float4*)&xs[(d + 2) * XSTR + q * 4];
                float4 x3 = *(const float4*)&xs[(d + 3) * XSTR + q * 4];
                acc[q*4+0] += x0.x * w0 + x1.x * w1 + x2.x * w2 + x3.x * w3;
                acc[q*4+1] += x0.y * w0 + x1.y * w1 + x2.y * w2 + x3.y * w3;
                acc[q*4+2] += x0.z * w0 + x1.z * w1 + x2.z * w2 + x3.z * w3;
                acc[q*4+3] += x0.w * w0 + x1.w * w1 + x2.w * w2 + x3.w * w3;
            }
        }
    }

    // gelu + store transposed hs[e][t]
#pragma unroll
    for (int q = 0; q < Q; q++) {
        float4 hv;
        hv.x = gelu_exact(acc[q * 4 + 0]);
        hv.y = gelu_exact(acc[q * 4 + 1]);
        hv.z = gelu_exact(acc[q * 4 + 2]);
        hv.w = gelu_exact(acc[q * 4 + 3]);
        *(float4*)&hs[tid * HSTR + q * 4] = hv;
    }
    __syncthreads();   // hs ready; xs reads done -> xs reusable as reduction buf

    // ---- layer 2: out[t][d] = sum_e hs[e][t] * W2[e][d] + b2[d] ----
    float acc2[Q * 4];
#pragma unroll
    for (int t = 0; t < Q * 4; t++) acc2[t] = 0.0f;

    {
        const int ebase = half << 7;
        const float* wp = W2 + (size_t)ebase * DMODEL + dcol;
        const float* hp = hs + ebase * HSTR;
#pragma unroll 1
        for (int ee = 0; ee < 128; ee += 4) {
            float w0 = wp[(ee + 0) * DMODEL];
            float w1 = wp[(ee + 1) * DMODEL];
            float w2 = wp[(ee + 2) * DMODEL];
            float w3 = wp[(ee + 3) * DMODEL];
#pragma unroll
            for (int q = 0; q < Q; q++) {
                float4 h0 = *(const float4*)&hp[(ee + 0) * HSTR + q * 4];
                float4 h1 = *(const float4*)&hp[(ee + 1) * HSTR + q * 4];
                float4 h2 = *(const float4*)&hp[(ee + 2) * HSTR + q * 4];
                float4 h3 = *(const float4*)&hp[(ee + 3) * HSTR + q * 4];
                acc2[q*4+0] += h0.x * w0 + h1.x * w1 + h2.x * w2 + h3.x * w3;
                acc2[q*4+1] += h0.y * w0 + h1.y * w1 + h2.y * w2 + h3.y * w3;
                acc2[q*4+2] += h0.z * w0 + h1.z * w1 + h2.z * w2 + h3.z * w3;
                acc2[q*4+3] += h0.w * w0 + h1.w * w1 + h2.w * w2 + h3.w * w3;
            }
        }
    }

    // half 1 dumps partials into xs (reused as [d][t] reduction buffer)
    if (half == 1) {
#pragma unroll
        for (int q = 0; q < Q; q++) {
            float4 pv;
            pv.x = acc2[q * 4 + 0]; pv.y = acc2[q * 4 + 1];
            pv.z = acc2[q * 4 + 2]; pv.w = acc2[q * 4 + 3];
            *(float4*)&xs[dcol * XSTR + q * 4] = pv;
        }
    }
    __syncthreads();

    if (half == 0) {
#pragma unroll
        for (int q = 0; q < Q; q++) {
            const float4 pv = *(const float4*)&xs[dcol * XSTR + q * 4];
            acc2[q * 4 + 0] += pv.x;
            acc2[q * 4 + 1] += pv.y;
            acc2[q * 4 + 2] += pv.z;
            acc2[q * 4 + 3] += pv.w;
        }
        for (int t = 0; t < T; t++)
            out[(size_t)toks[t] * DMODEL + dcol] = acc2[t] + b2v;  // coalesced
    }
    __syncthreads();  // protect toks/xs before next chunk
}

// One block per rule, 256 threads, 5 CTAs/SM (reg cap 51).
__global__ __launch_bounds__(256, 5) void ffn_kernel(
    const float* __restrict__ x,
    const void*  __restrict__ rules,
    const float* __restrict__ w1,
    const float* __restrict__ b1,
    const float* __restrict__ w2,
    const float* __restrict__ b2,
    float* __restrict__ out,
    int n)
{
    const int r   = blockIdx.x;
    const int tid = threadIdx.x;

    __shared__ float xs[DMODEL * XSTR];
    __shared__ float hs[EDIM * HSTR];
    __shared__ int   toks[CAP];
    __shared__ int   cnt;

    if (tid == 0) cnt = 0;
    __syncthreads();

    // ---- self-gather this rule's tokens (order irrelevant) ----
    if (g_is64 == 0) {
        const long long* rl = (const long long*)rules;
        for (int i = tid; i < n; i += 256)
            if ((int)rl[i] == r) { int p = atomicAdd(&cnt, 1); if (p < CAP) toks[p] = i; }
    } else {
        const int* rl = (const int*)rules;
        for (int i = tid; i < n; i += 256)
            if (rl[i] == r) { int p = atomicAdd(&cnt, 1); if (p < CAP) toks[p] = i; }
    }
    __syncthreads();

    const int count = min(cnt, CAP);
    if (count == 0) return;

    const int half = tid >> 7;
    const int dcol = tid & 127;

    const float* W1 = w1 + (size_t)r * DMODEL * EDIM;
    const float* W2 = w2 + (size_t)r * EDIM * DMODEL;
    const float b1v = b1[(size_t)r * EDIM + tid];
    const float b2v = b2[(size_t)r * DMODEL + dcol];

    for (int base = 0; base < count; base += TMAX) {
        const int T = min(TMAX, count - base);
        if (T <= 4) ffn_chunk<1>(x, W1, W2, b1v, b2v, xs, hs, toks + base, out, T, tid, half, dcol);
        else        ffn_chunk<2>(x, W1, W2, b1v, b2v, xs, hs, toks + base, out, T, tid, half, dcol);
    }
}

extern "C" void kernel_launch(void* const* d_in, const int* in_sizes, int n_in,
                              void* d_out, int out_size)
{
    const float* x     = (const float*)d_in[0];
    const void*  rules = d_in[1];
    const float* w1    = (const float*)d_in[2];
    const float* b1    = (const float*)d_in[3];
    const float* w2    = (const float*)d_in[4];
    const float* b2    = (const float*)d_in[5];
    float*       out   = (float*)d_out;

    const int n = in_sizes[1];

    detect_kernel<<<1, 256>>>((const unsigned int*)rules);  // probes 256 odd words (in-bounds either dtype)
    ffn_kernel<<<NRULES, 256>>>(x, rules, w1, b1, w2, b2, out, n);
}

// round 7
// speedup vs baseline: 2.9248x; 1.5420x over previous
#include <cuda_runtime.h>
#include <math.h>
#include <stdint.h>

#define NRULES 1024
#define DMODEL 128
#define EDIM   256
#define TMAX   16
#define CAP    96      // max tokens per rule per launch (P(Poisson(8)>96) ~ 0)
#define XSTR   20      // [d][t] tile stride (mult of 4 -> aligned float4)
#define HSTR   20      // [e][t] tile stride
#define CHUNKB 16384   // TMA chunk bytes
#define CHUNKF 4096    // TMA chunk floats
#define NSLOT  4       // ring depth

// dynamic smem layout (bytes)
#define WOFF   0
#define XOFF   (NSLOT * CHUNKB)                  // 65536
#define HOFF   (XOFF + DMODEL * XSTR * 4)        // 75776
#define TOKOFF (HOFF + EDIM * HSTR * 4)          // 96256
#define MBOFF  (TOKOFF + CAP * 4)                // 96640
#define SMEMSZ (MBOFF + NSLOT * 8 + 96)          // 96768

// 0 = int64 layout, 1 = int32. Monotonic; identical inputs every replay.
__device__ int g_is64 = 0;

__global__ void detect_kernel(const unsigned int* __restrict__ raw) {
    int i = threadIdx.x;
    if (raw[2 * i + 1] != 0u) atomicOr(&g_is64, 1);
}

__device__ __forceinline__ uint32_t smem_u32(const void* p) {
    uint32_t a;
    asm("{ .reg .u64 t; cvta.to.shared.u64 t, %1; cvt.u32.u64 %0, t; }" : "=r"(a) : "l"(p));
    return a;
}
__device__ __forceinline__ void mbar_init(uint32_t a, uint32_t cnt) {
    asm volatile("mbarrier.init.shared.b64 [%0], %1;" :: "r"(a), "r"(cnt) : "memory");
}
__device__ __forceinline__ void mbar_expect_tx(uint32_t a, uint32_t bytes) {
    asm volatile("mbarrier.arrive.expect_tx.shared.b64 _, [%0], %1;" :: "r"(a), "r"(bytes) : "memory");
}
__device__ __forceinline__ void bulk_g2s(uint32_t dst, const void* src, uint32_t bytes, uint32_t mbar) {
    asm volatile("cp.async.bulk.shared::cluster.global.mbarrier::complete_tx::bytes [%0], [%1], %2, [%3];"
                 :: "r"(dst), "l"(src), "r"(bytes), "r"(mbar) : "memory");
}
__device__ __forceinline__ void mbar_wait(uint32_t mbar, uint32_t parity) {
    asm volatile(
        "{\n\t.reg .pred P1;\n\t"
        "WAIT_%=:\n\t"
        "mbarrier.try_wait.parity.acquire.cta.shared::cta.b64 P1, [%0], %1, 0x989680;\n\t"
        "@P1 bra DONE_%=;\n\t"
        "bra WAIT_%=;\n\t"
        "DONE_%=:\n\t}"
        :: "r"(mbar), "r"(parity) : "memory");
}
__device__ __forceinline__ float gelu_exact(float v) {
    return 0.5f * v * (1.0f + erff(v * 0.70710678118654752f));
}

// One CTA per rule. 256 threads. Producer thread 0 streams W1|W2 chunks via
// cp.async.bulk; all threads consume from smem. 4x4 register blocking.
__global__ __launch_bounds__(256, 2) void ffn_kernel(
    const float* __restrict__ x,
    const void*  __restrict__ rules,
    const float* __restrict__ w1,
    const float* __restrict__ b1,
    const float* __restrict__ w2,
    const float* __restrict__ b2,
    float* __restrict__ out,
    int n)
{
    extern __shared__ __align__(128) char smem[];
    float* wbuf = (float*)(smem + WOFF);
    float* xs   = (float*)(smem + XOFF);
    float* hs   = (float*)(smem + HOFF);
    int*   toks = (int*)(smem + TOKOFF);
    const uint32_t sb = smem_u32(smem);
    const uint32_t mb = sb + MBOFF;

    __shared__ int cnt;

    const int r   = blockIdx.x;
    const int tid = threadIdx.x;

    if (tid < NSLOT) mbar_init(mb + tid * 8, 1);
    if (tid == 0) cnt = 0;
    __syncthreads();

    // ---- self-gather this rule's tokens (order irrelevant: tokens independent) ----
    if (g_is64 == 0) {
        const long long* rl = (const long long*)rules;
        for (int i = tid; i < n; i += 256)
            if ((int)rl[i] == r) { int p = atomicAdd(&cnt, 1); if (p < CAP) toks[p] = i; }
    } else {
        const int* rl = (const int*)rules;
        for (int i = tid; i < n; i += 256)
            if (rl[i] == r) { int p = atomicAdd(&cnt, 1); if (p < CAP) toks[p] = i; }
    }
    __syncthreads();

    const int count = min(cnt, CAP);
    if (count == 0) return;

    const float* W1 = w1 + (size_t)r * (DMODEL * EDIM);
    const float* W2 = w2 + (size_t)r * (EDIM * DMODEL);

    const int npass  = (count + TMAX - 1) / TMAX;   // ~always 1
    const int totalK = npass * 16;

    // producer prologue: fill the ring
    if (tid == 0) {
        const int kmax = totalK < NSLOT ? totalK : NSLOT;
        for (int K = 0; K < kmax; K++) {
            const int c = K & 15;
            const float* src = (c < 8) ? (W1 + c * CHUNKF) : (W2 + (c - 8) * CHUNKF);
            mbar_expect_tx(mb + (K & 3) * 8, CHUNKB);
            bulk_g2s(sb + WOFF + (K & 3) * CHUNKB, src, CHUNKB, mb + (K & 3) * 8);
        }
    }

    // role constants
    const int e0 = (tid & 63) * 4, tq1 = tid >> 6, t1 = tq1 * 4;               // layer1
    const int d0 = (tid & 31) * 4, tq2 = (tid >> 5) & 3, eh = tid >> 7;        // layer2
    const int t2 = tq2 * 4;

    for (int pass = 0; pass < npass; pass++) {
        const int base = pass * TMAX;
        const int T  = min(TMAX, count - base);
        const int NQ = (T + 3) >> 2;

        // ---- x tile, transposed xs[d][t] ----
        for (int i = tid; i < NQ * 4 * DMODEL; i += 256) {
            int t = i >> 7, d = i & (DMODEL - 1);
            xs[d * XSTR + t] = (t < T) ? x[(size_t)toks[base + t] * DMODEL + d] : 0.0f;
        }
        __syncthreads();

        // ---- layer 1: chunks 0..7 (each 16 d-rows x 256 e) ----
        float acc[16];
        if (tq1 < NQ) {
            const float4 bv = *(const float4*)&b1[(size_t)r * EDIM + e0];
#pragma unroll
            for (int k = 0; k < 4; k++) {
                acc[0 + k] = bv.x; acc[4 + k] = bv.y; acc[8 + k] = bv.z; acc[12 + k] = bv.w;
            }
        }
        for (int c = 0; c < 8; c++) {
            const int K = pass * 16 + c, slot = K & 3;
            mbar_wait(mb + slot * 8, (K >> 2) & 1);
            if (tq1 < NQ) {
                const float* Wc = wbuf + slot * CHUNKF;     // [16][256]
#pragma unroll
                for (int dd = 0; dd < 16; dd++) {
                    const float4 w4 = *(const float4*)&Wc[dd * EDIM + e0];
                    const float4 x4 = *(const float4*)&xs[(c * 16 + dd) * XSTR + t1];
                    const float wj[4] = {w4.x, w4.y, w4.z, w4.w};
                    const float xk[4] = {x4.x, x4.y, x4.z, x4.w};
#pragma unroll
                    for (int j = 0; j < 4; j++)
#pragma unroll
                        for (int k = 0; k < 4; k++)
                            acc[j * 4 + k] += wj[j] * xk[k];
                }
            }
            if (c == 7 && tq1 < NQ) {       // gelu + hs store before the barrier
#pragma unroll
                for (int j = 0; j < 4; j++) {
                    float4 hv;
                    hv.x = gelu_exact(acc[j * 4 + 0]);
                    hv.y = gelu_exact(acc[j * 4 + 1]);
                    hv.z = gelu_exact(acc[j * 4 + 2]);
                    hv.w = gelu_exact(acc[j * 4 + 3]);
                    *(float4*)&hs[(e0 + j) * HSTR + t1] = hv;
                }
            }
            __syncthreads();                 // all reads of slot done (+ hs visible at c==7)
            if (tid == 0 && K + NSLOT < totalK) {
                const int K2 = K + NSLOT, c2 = K2 & 15;
                const float* src = (c2 < 8) ? (W1 + c2 * CHUNKF) : (W2 + (c2 - 8) * CHUNKF);
                mbar_expect_tx(mb + (K2 & 3) * 8, CHUNKB);
                bulk_g2s(sb + WOFF + (K2 & 3) * CHUNKB, src, CHUNKB, mb + (K2 & 3) * 8);
            }
        }

        // ---- layer 2: chunks 8..15 (each 32 e-rows x 128 d), e split in halves ----
        float acc2[16];
#pragma unroll
        for (int i = 0; i < 16; i++) acc2[i] = 0.0f;

        for (int c = 8; c < 16; c++) {
            const int K = pass * 16 + c, slot = K & 3;
            mbar_wait(mb + slot * 8, (K >> 2) & 1);
            if (tq2 < NQ && ((c - 8) >> 2) == eh) {
                const float* Wc = wbuf + slot * CHUNKF;     // [32][128]
                const int erow = (c - 8) * 32;
#pragma unroll
                for (int ee = 0; ee < 32; ee++) {
                    const float4 w4 = *(const float4*)&Wc[ee * DMODEL + d0];
                    const float4 h4 = *(const float4*)&hs[(erow + ee) * HSTR + t2];
                    const float wj[4] = {w4.x, w4.y, w4.z, w4.w};
                    const float hk[4] = {h4.x, h4.y, h4.z, h4.w};
#pragma unroll
                    for (int j = 0; j < 4; j++)
#pragma unroll
                        for (int k = 0; k < 4; k++)
                            acc2[j * 4 + k] += wj[j] * hk[k];
                }
            }
            __syncthreads();
            if (tid == 0 && K + NSLOT < totalK) {
                const int K2 = K + NSLOT, c2 = K2 & 15;
                const float* src = (c2 < 8) ? (W1 + c2 * CHUNKF) : (W2 + (c2 - 8) * CHUNKF);
                mbar_expect_tx(mb + (K2 & 3) * 8, CHUNKB);
                bulk_g2s(sb + WOFF + (K2 & 3) * CHUNKB, src, CHUNKB, mb + (K2 & 3) * 8);
            }
        }

        // ---- reduce e-halves via xs, add bias, store ----
        if (eh == 1 && tq2 < NQ) {
#pragma unroll
            for (int j = 0; j < 4; j++) {
                float4 pv;
                pv.x = acc2[j * 4 + 0]; pv.y = acc2[j * 4 + 1];
                pv.z = acc2[j * 4 + 2]; pv.w = acc2[j * 4 + 3];
                *(float4*)&xs[(d0 + j) * XSTR + t2] = pv;
            }
        }
        __syncthreads();
        if (eh == 0 && tq2 < NQ) {
            const float4 b2v = *(const float4*)&b2[(size_t)r * DMODEL + d0];
#pragma unroll
            for (int j = 0; j < 4; j++) {
                const float4 pv = *(const float4*)&xs[(d0 + j) * XSTR + t2];
                acc2[j * 4 + 0] += pv.x; acc2[j * 4 + 1] += pv.y;
                acc2[j * 4 + 2] += pv.z; acc2[j * 4 + 3] += pv.w;
            }
#pragma unroll
            for (int k = 0; k < 4; k++) {
                const int t = t2 + k;
                if (t < T) {
                    float4 o;
                    o.x = acc2[0 + k]  + b2v.x;
                    o.y = acc2[4 + k]  + b2v.y;
                    o.z = acc2[8 + k]  + b2v.z;
                    o.w = acc2[12 + k] + b2v.w;
                    *(float4*)&out[(size_t)toks[base + t] * DMODEL + d0] = o;
                }
            }
        }
        __syncthreads();   // xs reuse safety for next pass
    }
}

extern "C" void kernel_launch(void* const* d_in, const int* in_sizes, int n_in,
                              void* d_out, int out_size)
{
    const float* x     = (const float*)d_in[0];
    const void*  rules = d_in[1];
    const float* w1    = (const float*)d_in[2];
    const float* b1    = (const float*)d_in[3];
    const float* w2    = (const float*)d_in[4];
    const float* b2    = (const float*)d_in[5];
    float*       out   = (float*)d_out;

    const int n = in_sizes[1];

    cudaFuncSetAttribute(ffn_kernel, cudaFuncAttributeMaxDynamicSharedMemorySize, SMEMSZ);

    detect_kernel<<<1, 256>>>((const unsigned int*)rules);  // probes 256 odd words (in-bounds either dtype)
    ffn_kernel<<<NRULES, 256, SMEMSZ>>>(x, rules, w1, b1, w2, b2, out, n);
}